// round 13
// baseline (speedup 1.0000x reference)
#include <cuda_runtime.h>
#include <cuda_bf16.h>
#include <cstdint>
#include <math.h>

// Problem constants
#define BB 64
#define SS 512
#define II 512
#define HH 512
#define LL 2
#define MROWS (BB * LL)          // 128 recurrence rows
#define MX (BB * SS)             // 32768 rows of xa GEMM

// ---------------- scratch (static device memory; no allocs allowed) ----------
__device__ float g_xa[(size_t)MX * HH];       // 64 MB: xa = x @ W_ih^T + b_ih
__device__ float g_h[2][MROWS * HH];          // double-buffered recurrent state

// per-CTA monotonic step flags: g_sf[rb][gb] = last step published (reset/launch)
__device__ __align__(32) unsigned g_sf[16][8];

__device__ __forceinline__ unsigned cvt_tf32(float f) {
    unsigned u;
    asm("cvt.rna.tf32.f32 %0, %1;" : "=r"(u) : "f"(f));
    return u;
}

// =============================================================================
// Kernel R: reset step flags (head of every launch; graph-replay safety)
// =============================================================================
__global__ void reset_flags_kernel()
{
    if (threadIdx.x < 128)
        ((unsigned*)g_sf)[threadIdx.x] = 0u;
}

// =============================================================================
// Kernel A: xa[m][n] = sum_k x[m][k] * W_ih[n][k] + b_ih[n]   via tf32 mma.sync
// (unchanged from round 9 — proven)
// =============================================================================
__global__ void __launch_bounds__(256) gemm_xa_mma_kernel(
    const float* __restrict__ X,      // [MX][II]
    const float* __restrict__ Wih,    // [HH][II]
    const float* __restrict__ bias)   // [HH]
{
    const int m0   = blockIdx.y * 128;
    const int n0   = blockIdx.x * 128;
    const int w    = threadIdx.x >> 5;
    const int lane = threadIdx.x & 31;
    const int g    = lane >> 2;        // groupID 0..7
    const int t    = lane & 3;         // thread-in-group 0..3
    const int wr   = w >> 2;           // 0..1  -> 64 m-rows
    const int wc   = w & 3;            // 0..3  -> 32 n-cols
    const int mbase = m0 + wr * 64;
    const int nbase = n0 + wc * 32;

    float acc[4][4][4];
#pragma unroll
    for (int mf = 0; mf < 4; mf++)
#pragma unroll
        for (int nf = 0; nf < 4; nf++)
#pragma unroll
            for (int r = 0; r < 4; r++) acc[mf][nf][r] = 0.f;

    const float* Xa = X + (size_t)(mbase + g) * II;
    const float* Xb = X + (size_t)(mbase + g + 8) * II;
    const float* Wb = Wih + (size_t)(nbase + g) * II;

#pragma unroll 2
    for (int kt = 0; kt < 64; kt++) {
        const int k0 = kt * 8;

        unsigned a[4][4];
#pragma unroll
        for (int mf = 0; mf < 4; mf++) {
            const int ro = mf * 16 * II;
            a[mf][0] = cvt_tf32(__ldg(Xa + ro + k0 + t));
            a[mf][1] = cvt_tf32(__ldg(Xb + ro + k0 + t));
            a[mf][2] = cvt_tf32(__ldg(Xa + ro + k0 + t + 4));
            a[mf][3] = cvt_tf32(__ldg(Xb + ro + k0 + t + 4));
        }
        unsigned b[4][2];
#pragma unroll
        for (int nf = 0; nf < 4; nf++) {
            const int no = nf * 8 * II;
            b[nf][0] = cvt_tf32(__ldg(Wb + no + k0 + t));
            b[nf][1] = cvt_tf32(__ldg(Wb + no + k0 + t + 4));
        }
#pragma unroll
        for (int mf = 0; mf < 4; mf++)
#pragma unroll
            for (int nf = 0; nf < 4; nf++) {
                asm volatile(
                    "mma.sync.aligned.m16n8k8.row.col.f32.tf32.tf32.f32 "
                    "{%0,%1,%2,%3}, {%4,%5,%6,%7}, {%8,%9}, {%0,%1,%2,%3};"
                    : "+f"(acc[mf][nf][0]), "+f"(acc[mf][nf][1]),
                      "+f"(acc[mf][nf][2]), "+f"(acc[mf][nf][3])
                    : "r"(a[mf][0]), "r"(a[mf][1]), "r"(a[mf][2]), "r"(a[mf][3]),
                      "r"(b[nf][0]), "r"(b[nf][1]));
            }
    }

#pragma unroll
    for (int nf = 0; nf < 4; nf++) {
        const int col = nbase + nf * 8 + 2 * t;
        const float2 bv = *(const float2*)&bias[col];
#pragma unroll
        for (int mf = 0; mf < 4; mf++) {
            const int row0 = mbase + mf * 16 + g;
            float2 d01, d23;
            d01.x = acc[mf][nf][0] + bv.x;
            d01.y = acc[mf][nf][1] + bv.y;
            d23.x = acc[mf][nf][2] + bv.x;
            d23.y = acc[mf][nf][3] + bv.y;
            *(float2*)&g_xa[(size_t)row0 * HH + col]       = d01;
            *(float2*)&g_xa[(size_t)(row0 + 8) * HH + col] = d23;
        }
    }
}

// =============================================================================
// Kernel B: persistent recurrence, v8 (tensor core + flag-array barrier +
// split MMA accumulator chains).
// 128 CTAs = 16 row-groups (rb) x 8 col-blocks (gb).
// CTA (rb,gb): batch rows rb*8..+7 (n), W cols gb*64..+63 (m), K=512.
// 8 warps = 4 m-tiles (mw) x 2 k-halves (kw).  W tf32 A-frags in registers.
// Sync: each CTA publishes h slice then st.release its step flag; consumers
// poll all 8 group flags (8 relaxed loads, one L2 round trip) + acq fence.
// =============================================================================
#define GB_CTAS 128

__global__ void __launch_bounds__(256, 1) rnn_persistent_kernel(
    const float* __restrict__ W_hh,   // [HH][HH]
    const float* __restrict__ b_hh,   // [HH]
    float* __restrict__ out)          // y then h_last
{
    __shared__ unsigned hsu[8 * 516];     // staged h rows, tf32, padded
    __shared__ float red[2 * 64 * 8];     // [kw][m][n]

    const int tid  = threadIdx.x;
    const int w    = tid >> 5;
    const int lane = tid & 31;
    const int g    = lane >> 2;        // 0..7
    const int t    = lane & 3;         // 0..3
    const int mw   = w & 3;            // m-tile 0..3
    const int kw   = w >> 2;           // k-half 0..1
    const int kb   = kw * 256;

    const int gb  = blockIdx.x & 7;
    const int rb  = blockIdx.x >> 3;
    const int g0  = gb * 64;
    const int row_base = rb * 8;

    // ---- one-time: load this warp's W A-fragments into registers ----
    unsigned wa[32][4];
    {
        const float* w0p = W_hh + (size_t)(g0 + mw * 16 + g) * HH + kb;
        const float* w1p = w0p + 8 * HH;
#pragma unroll
        for (int ks = 0; ks < 32; ks++) {
            wa[ks][0] = cvt_tf32(__ldg(w0p + ks * 8 + t));
            wa[ks][1] = cvt_tf32(__ldg(w1p + ks * 8 + t));
            wa[ks][2] = cvt_tf32(__ldg(w0p + ks * 8 + t + 4));
            wa[ks][3] = cvt_tf32(__ldg(w1p + ks * 8 + t + 4));
        }
    }

    // ---- epilogue mapping: outputs (n=orow, m=oc, oc+1) ----
    const int orow  = tid >> 5;        // batch row 0..7
    const int oc    = 2 * (tid & 31);  // W col pair 0..62
    const int grow  = row_base + orow;
    const int b_idx = grow >> 1;
    const int l_idx = grow & 1;
    const int gcol  = g0 + oc;

    const float2 bg  = *(const float2*)&b_hh[gcol];
    float2 xav = *(const float2*)&g_xa[((size_t)b_idx * SS + 0) * HH + gcol];

    unsigned* my_flag = &g_sf[rb][gb];
    const unsigned* gflags = &g_sf[rb][0];

    const size_t Y_ELEMS = (size_t)BB * SS * LL * HH;
    __syncthreads();

    for (int s = 0; s < SS; s++) {
        float v0, v1;
        if (s == 0) {
            v0 = tanhf(xav.x + bg.x);
            v1 = tanhf(xav.y + bg.y);
        } else {
            // wait until all 8 group CTAs have published step s
            if (tid == 0) {
                const unsigned target = (unsigned)s;
                bool ok;
                do {
                    unsigned f[8];
#pragma unroll
                    for (int p = 0; p < 8; p++)
                        asm volatile("ld.relaxed.gpu.u32 %0, [%1];"
                                     : "=r"(f[p]) : "l"(gflags + p));
                    ok = true;
#pragma unroll
                    for (int p = 0; p < 8; p++) ok &= (f[p] >= target);
                } while (!ok);
                asm volatile("fence.acq_rel.gpu;" ::: "memory");
            }
            __syncthreads();

            // stage h rows (8 x 512) from L2, converting to tf32
            {
                const float4* src =
                    (const float4*)(&g_h[s & 1][(size_t)row_base * HH]);
#pragma unroll
                for (int j = 0; j < 4; j++) {
                    const int idx = tid + j * 256;      // 0..1023 float4s
                    const int r   = idx >> 7;
                    const int kk  = (idx & 127) * 4;
                    const float4 hv = __ldcg(src + idx);
                    uint4 u;
                    u.x = cvt_tf32(hv.x); u.y = cvt_tf32(hv.y);
                    u.z = cvt_tf32(hv.z); u.w = cvt_tf32(hv.w);
                    *(uint4*)&hsu[r * 516 + kk] = u;
                }
            }
            __syncthreads();

            // tensor-core accumulate, TWO independent chains (ks and ks+16)
            float c00 = 0.f, c01 = 0.f, c02 = 0.f, c03 = 0.f;
            float c10 = 0.f, c11 = 0.f, c12 = 0.f, c13 = 0.f;
            const unsigned* hb = hsu + g * 516 + kb + t;
#pragma unroll
            for (int ks = 0; ks < 16; ks++) {
                const unsigned b0a = hb[ks * 8];
                const unsigned b1a = hb[ks * 8 + 4];
                const unsigned b0b = hb[(ks + 16) * 8];
                const unsigned b1b = hb[(ks + 16) * 8 + 4];
                asm volatile(
                    "mma.sync.aligned.m16n8k8.row.col.f32.tf32.tf32.f32 "
                    "{%0,%1,%2,%3}, {%4,%5,%6,%7}, {%8,%9}, {%0,%1,%2,%3};"
                    : "+f"(c00), "+f"(c01), "+f"(c02), "+f"(c03)
                    : "r"(wa[ks][0]), "r"(wa[ks][1]),
                      "r"(wa[ks][2]), "r"(wa[ks][3]),
                      "r"(b0a), "r"(b1a));
                asm volatile(
                    "mma.sync.aligned.m16n8k8.row.col.f32.tf32.tf32.f32 "
                    "{%0,%1,%2,%3}, {%4,%5,%6,%7}, {%8,%9}, {%0,%1,%2,%3};"
                    : "+f"(c10), "+f"(c11), "+f"(c12), "+f"(c13)
                    : "r"(wa[ks + 16][0]), "r"(wa[ks + 16][1]),
                      "r"(wa[ks + 16][2]), "r"(wa[ks + 16][3]),
                      "r"(b0b), "r"(b1b));
            }
            const float a0 = c00 + c10;
            const float a1 = c01 + c11;
            const float a2 = c02 + c12;
            const float a3 = c03 + c13;

            // scatter partials: red[kw][m][n]
            {
                float* rp = red + kw * 512;
                *(float2*)&rp[(mw * 16 + g) * 8 + 2 * t]     = make_float2(a0, a1);
                *(float2*)&rp[(mw * 16 + g + 8) * 8 + 2 * t] = make_float2(a2, a3);
            }
            __syncthreads();

            // k-half reduce for outputs (m=oc,oc+1; n=orow)
            const float s0 = red[oc * 8 + orow]       + red[512 + oc * 8 + orow];
            const float s1 = red[(oc + 1) * 8 + orow] + red[512 + (oc + 1) * 8 + orow];
            v0 = tanhf(s0 + xav.x + bg.x);
            v1 = tanhf(s1 + xav.y + bg.y);
        }

        // publish h for next step (straight to L2)
        {
            float2* hdst = (float2*)&g_h[(s + 1) & 1][(size_t)grow * HH + gcol];
            asm volatile("st.global.cg.v2.f32 [%0], {%1, %2};"
                         :: "l"(hdst), "f"(v0), "f"(v1));
        }
        __syncthreads();

        // publish step flag (release after syncthreads -> covers all h stores)
        if (s < SS - 1 && tid == 0) {
            asm volatile("st.release.gpu.u32 [%0], %1;"
                         :: "l"(my_flag), "r"((unsigned)(s + 1)));
        }

        // epilogue overlaps peers' polls: y writes + next xa prefetch
        {
            float2 yv; yv.x = v0; yv.y = v1;
            *(float2*)&out[(((size_t)b_idx * SS + s) * LL + l_idx) * HH + gcol] = yv;
            if (s == SS - 1) {
                *(float2*)&out[Y_ELEMS + (size_t)grow * HH + gcol] = yv;
            } else {
                xav = *(const float2*)&g_xa[((size_t)b_idx * SS + (s + 1)) * HH + gcol];
            }
        }
    }
}

// =============================================================================
// launch
// =============================================================================
extern "C" void kernel_launch(void* const* d_in, const int* in_sizes, int n_in,
                              void* d_out, int out_size)
{
    const float* x    = (const float*)d_in[0];
    const float* W_ih = (const float*)d_in[1];
    const float* b_ih = (const float*)d_in[2];
    const float* W_hh = (const float*)d_in[3];
    const float* b_hh = (const float*)d_in[4];
    float* out = (float*)d_out;

    // Reset step flags (graph-replay safety)
    reset_flags_kernel<<<1, 128>>>();

    // Kernel A: xa = x @ W_ih^T + b_ih  (tf32 mma.sync)
    dim3 gridA(HH / 128, MX / 128);   // (4, 256)
    gemm_xa_mma_kernel<<<gridA, 256>>>(x, W_ih, b_ih);

    // Kernel B: persistent recurrence (tensor core, flag-array barrier)
    rnn_persistent_kernel<<<GB_CTAS, 256>>>(W_hh, b_hh, out);
}

// round 14
// speedup vs baseline: 1.1191x; 1.1191x over previous
#include <cuda_runtime.h>
#include <cuda_bf16.h>
#include <cstdint>
#include <math.h>

// Problem constants
#define BB 64
#define SS 512
#define II 512
#define HH 512
#define LL 2
#define MROWS (BB * LL)
#define MX (BB * SS)

// ---------------- scratch (static device memory; no allocs allowed) ----------
__device__ float g_xa[(size_t)MX * HH];       // 64 MB: xa = x @ W_ih^T + b_ih
__device__ float g_h[2][MROWS * HH];          // double-buffered recurrent state

// per-CTA monotonic step flags
__device__ __align__(32) unsigned g_sf[16][8];

__device__ __forceinline__ unsigned cvt_tf32(float f) {
    unsigned u;
    asm("cvt.rna.tf32.f32 %0, %1;" : "=r"(u) : "f"(f));
    return u;
}

// =============================================================================
// Kernel R: reset step flags (graph-replay safety)
// =============================================================================
__global__ void reset_flags_kernel()
{
    if (threadIdx.x < 128)
        ((unsigned*)g_sf)[threadIdx.x] = 0u;
}

// =============================================================================
// Kernel A v2: xa = x @ W_ih^T + b_ih, tf32 mma.sync with SMEM staging.
// CTA 128x128, k-chunk 16, double-buffered tiles (tf32, stride 17).
// 8 warps = 2 (wr: 64 m) x 4 (wc: 32 n); warp tile 64x32.
// Staging: thread (srow=tid>>1, skq=(tid&1)*8) loads 2 float4 per tile,
// coalesced; converts to tf32 at STS time.
// =============================================================================
#define CH 16
#define APAD 17

__global__ void __launch_bounds__(256) gemm_xa_mma_kernel(
    const float* __restrict__ X,      // [MX][II]
    const float* __restrict__ Wih,    // [HH][II]
    const float* __restrict__ bias)   // [HH]
{
    __shared__ unsigned As[2][128 * APAD];
    __shared__ unsigned Bs[2][128 * APAD];

    const int m0   = blockIdx.y * 128;
    const int n0   = blockIdx.x * 128;
    const int tid  = threadIdx.x;
    const int w    = tid >> 5;
    const int lane = tid & 31;
    const int g    = lane >> 2;        // 0..7
    const int t    = lane & 3;         // 0..3
    const int wr   = w >> 2;           // 0..1
    const int wc   = w & 3;            // 0..3

    const int srow = tid >> 1;         // 0..127
    const int skq  = (tid & 1) * 8;    // 0 or 8

    const float* Ag = X   + (size_t)(m0 + srow) * II + skq;
    const float* Bg = Wih + (size_t)(n0 + srow) * II + skq;

    float acc[4][4][4];
#pragma unroll
    for (int mf = 0; mf < 4; mf++)
#pragma unroll
        for (int nf = 0; nf < 4; nf++)
#pragma unroll
            for (int r = 0; r < 4; r++) acc[mf][nf][r] = 0.f;

    // ---- stage chunk 0 ----
    {
        const float4 av0 = *(const float4*)(Ag + 0);
        const float4 av1 = *(const float4*)(Ag + 4);
        const float4 bv0 = *(const float4*)(Bg + 0);
        const float4 bv1 = *(const float4*)(Bg + 4);
        unsigned* ad = &As[0][srow * APAD + skq];
        unsigned* bd = &Bs[0][srow * APAD + skq];
        ad[0] = cvt_tf32(av0.x); ad[1] = cvt_tf32(av0.y);
        ad[2] = cvt_tf32(av0.z); ad[3] = cvt_tf32(av0.w);
        ad[4] = cvt_tf32(av1.x); ad[5] = cvt_tf32(av1.y);
        ad[6] = cvt_tf32(av1.z); ad[7] = cvt_tf32(av1.w);
        bd[0] = cvt_tf32(bv0.x); bd[1] = cvt_tf32(bv0.y);
        bd[2] = cvt_tf32(bv0.z); bd[3] = cvt_tf32(bv0.w);
        bd[4] = cvt_tf32(bv1.x); bd[5] = cvt_tf32(bv1.y);
        bd[6] = cvt_tf32(bv1.z); bd[7] = cvt_tf32(bv1.w);
    }
    __syncthreads();

    const int abase0 = (wr * 64 + g) * APAD + t;   // + mf*16*APAD (+8*APAD, +4)
    const int bbase0 = (wc * 32 + g) * APAD + t;   // + nf*8*APAD  (+4)

    for (int c = 0; c < 32; c++) {
        // prefetch next chunk gmem -> regs
        float4 av0, av1, bv0, bv1;
        const bool more = (c < 31);
        if (more) {
            const int kc = (c + 1) * CH;
            av0 = *(const float4*)(Ag + kc);
            av1 = *(const float4*)(Ag + kc + 4);
            bv0 = *(const float4*)(Bg + kc);
            bv1 = *(const float4*)(Bg + kc + 4);
        }

        // compute on buffer c&1
        const unsigned* Ab = As[c & 1];
        const unsigned* Bb = Bs[c & 1];
#pragma unroll
        for (int ks = 0; ks < 2; ks++) {
            const int ko = ks * 8;
            unsigned af[4][4];
#pragma unroll
            for (int mf = 0; mf < 4; mf++) {
                const int base = abase0 + mf * 16 * APAD + ko;
                af[mf][0] = Ab[base];
                af[mf][1] = Ab[base + 8 * APAD];
                af[mf][2] = Ab[base + 4];
                af[mf][3] = Ab[base + 8 * APAD + 4];
            }
            unsigned bf[4][2];
#pragma unroll
            for (int nf = 0; nf < 4; nf++) {
                const int base = bbase0 + nf * 8 * APAD + ko;
                bf[nf][0] = Bb[base];
                bf[nf][1] = Bb[base + 4];
            }
#pragma unroll
            for (int mf = 0; mf < 4; mf++)
#pragma unroll
                for (int nf = 0; nf < 4; nf++) {
                    asm volatile(
                        "mma.sync.aligned.m16n8k8.row.col.f32.tf32.tf32.f32 "
                        "{%0,%1,%2,%3}, {%4,%5,%6,%7}, {%8,%9}, {%0,%1,%2,%3};"
                        : "+f"(acc[mf][nf][0]), "+f"(acc[mf][nf][1]),
                          "+f"(acc[mf][nf][2]), "+f"(acc[mf][nf][3])
                        : "r"(af[mf][0]), "r"(af[mf][1]),
                          "r"(af[mf][2]), "r"(af[mf][3]),
                          "r"(bf[nf][0]), "r"(bf[nf][1]));
                }
        }

        if (more) {
            unsigned* ad = &As[(c + 1) & 1][srow * APAD + skq];
            unsigned* bd = &Bs[(c + 1) & 1][srow * APAD + skq];
            ad[0] = cvt_tf32(av0.x); ad[1] = cvt_tf32(av0.y);
            ad[2] = cvt_tf32(av0.z); ad[3] = cvt_tf32(av0.w);
            ad[4] = cvt_tf32(av1.x); ad[5] = cvt_tf32(av1.y);
            ad[6] = cvt_tf32(av1.z); ad[7] = cvt_tf32(av1.w);
            bd[0] = cvt_tf32(bv0.x); bd[1] = cvt_tf32(bv0.y);
            bd[2] = cvt_tf32(bv0.z); bd[3] = cvt_tf32(bv0.w);
            bd[4] = cvt_tf32(bv1.x); bd[5] = cvt_tf32(bv1.y);
            bd[6] = cvt_tf32(bv1.z); bd[7] = cvt_tf32(bv1.w);
            __syncthreads();
        }
    }

    // epilogue: add bias, store float2 pairs
    const int mbase = m0 + wr * 64;
    const int nbase = n0 + wc * 32;
#pragma unroll
    for (int nf = 0; nf < 4; nf++) {
        const int col = nbase + nf * 8 + 2 * t;
        const float2 bv = *(const float2*)&bias[col];
#pragma unroll
        for (int mf = 0; mf < 4; mf++) {
            const int row0 = mbase + mf * 16 + g;
            float2 d01, d23;
            d01.x = acc[mf][nf][0] + bv.x;
            d01.y = acc[mf][nf][1] + bv.y;
            d23.x = acc[mf][nf][2] + bv.x;
            d23.y = acc[mf][nf][3] + bv.y;
            *(float2*)&g_xa[(size_t)row0 * HH + col]       = d01;
            *(float2*)&g_xa[(size_t)(row0 + 8) * HH + col] = d23;
        }
    }
}

// =============================================================================
// Kernel B: persistent recurrence (round-12 version, unchanged — best known).
// =============================================================================
#define GB_CTAS 128

__global__ void __launch_bounds__(256, 1) rnn_persistent_kernel(
    const float* __restrict__ W_hh,   // [HH][HH]
    const float* __restrict__ b_hh,   // [HH]
    float* __restrict__ out)          // y then h_last
{
    __shared__ unsigned hsu[8 * 516];     // staged h rows, tf32, padded
    __shared__ float red[2 * 64 * 8];     // [kw][m][n]

    const int tid  = threadIdx.x;
    const int w    = tid >> 5;
    const int lane = tid & 31;
    const int g    = lane >> 2;
    const int t    = lane & 3;
    const int mw   = w & 3;
    const int kw   = w >> 2;
    const int kb   = kw * 256;

    const int gb  = blockIdx.x & 7;
    const int rb  = blockIdx.x >> 3;
    const int g0  = gb * 64;
    const int row_base = rb * 8;

    // one-time: W A-fragments into registers
    unsigned wa[32][4];
    {
        const float* w0p = W_hh + (size_t)(g0 + mw * 16 + g) * HH + kb;
        const float* w1p = w0p + 8 * HH;
#pragma unroll
        for (int ks = 0; ks < 32; ks++) {
            wa[ks][0] = cvt_tf32(__ldg(w0p + ks * 8 + t));
            wa[ks][1] = cvt_tf32(__ldg(w1p + ks * 8 + t));
            wa[ks][2] = cvt_tf32(__ldg(w0p + ks * 8 + t + 4));
            wa[ks][3] = cvt_tf32(__ldg(w1p + ks * 8 + t + 4));
        }
    }

    const int orow  = tid >> 5;
    const int oc    = 2 * (tid & 31);
    const int grow  = row_base + orow;
    const int b_idx = grow >> 1;
    const int l_idx = grow & 1;
    const int gcol  = g0 + oc;

    const float2 bg  = *(const float2*)&b_hh[gcol];
    float2 xav = *(const float2*)&g_xa[((size_t)b_idx * SS + 0) * HH + gcol];

    unsigned* my_flag = &g_sf[rb][gb];
    const unsigned* gflags = &g_sf[rb][0];

    const size_t Y_ELEMS = (size_t)BB * SS * LL * HH;
    __syncthreads();

    for (int s = 0; s < SS; s++) {
        float v0, v1;
        if (s == 0) {
            v0 = tanhf(xav.x + bg.x);
            v1 = tanhf(xav.y + bg.y);
        } else {
            if (tid == 0) {
                const unsigned target = (unsigned)s;
                bool ok;
                do {
                    unsigned f[8];
#pragma unroll
                    for (int p = 0; p < 8; p++)
                        asm volatile("ld.relaxed.gpu.u32 %0, [%1];"
                                     : "=r"(f[p]) : "l"(gflags + p));
                    ok = true;
#pragma unroll
                    for (int p = 0; p < 8; p++) ok &= (f[p] >= target);
                } while (!ok);
                asm volatile("fence.acq_rel.gpu;" ::: "memory");
            }
            __syncthreads();

            // stage h rows (8 x 512) from L2, converting to tf32
            {
                const float4* src =
                    (const float4*)(&g_h[s & 1][(size_t)row_base * HH]);
#pragma unroll
                for (int j = 0; j < 4; j++) {
                    const int idx = tid + j * 256;
                    const int r   = idx >> 7;
                    const int kk  = (idx & 127) * 4;
                    const float4 hv = __ldcg(src + idx);
                    uint4 u;
                    u.x = cvt_tf32(hv.x); u.y = cvt_tf32(hv.y);
                    u.z = cvt_tf32(hv.z); u.w = cvt_tf32(hv.w);
                    *(uint4*)&hsu[r * 516 + kk] = u;
                }
            }
            __syncthreads();

            // tensor-core accumulate, two chains
            float c00 = 0.f, c01 = 0.f, c02 = 0.f, c03 = 0.f;
            float c10 = 0.f, c11 = 0.f, c12 = 0.f, c13 = 0.f;
            const unsigned* hb = hsu + g * 516 + kb + t;
#pragma unroll
            for (int ks = 0; ks < 16; ks++) {
                const unsigned b0a = hb[ks * 8];
                const unsigned b1a = hb[ks * 8 + 4];
                const unsigned b0b = hb[(ks + 16) * 8];
                const unsigned b1b = hb[(ks + 16) * 8 + 4];
                asm volatile(
                    "mma.sync.aligned.m16n8k8.row.col.f32.tf32.tf32.f32 "
                    "{%0,%1,%2,%3}, {%4,%5,%6,%7}, {%8,%9}, {%0,%1,%2,%3};"
                    : "+f"(c00), "+f"(c01), "+f"(c02), "+f"(c03)
                    : "r"(wa[ks][0]), "r"(wa[ks][1]),
                      "r"(wa[ks][2]), "r"(wa[ks][3]),
                      "r"(b0a), "r"(b1a));
                asm volatile(
                    "mma.sync.aligned.m16n8k8.row.col.f32.tf32.tf32.f32 "
                    "{%0,%1,%2,%3}, {%4,%5,%6,%7}, {%8,%9}, {%0,%1,%2,%3};"
                    : "+f"(c10), "+f"(c11), "+f"(c12), "+f"(c13)
                    : "r"(wa[ks + 16][0]), "r"(wa[ks + 16][1]),
                      "r"(wa[ks + 16][2]), "r"(wa[ks + 16][3]),
                      "r"(b0b), "r"(b1b));
            }
            const float a0 = c00 + c10;
            const float a1 = c01 + c11;
            const float a2 = c02 + c12;
            const float a3 = c03 + c13;

            {
                float* rp = red + kw * 512;
                *(float2*)&rp[(mw * 16 + g) * 8 + 2 * t]     = make_float2(a0, a1);
                *(float2*)&rp[(mw * 16 + g + 8) * 8 + 2 * t] = make_float2(a2, a3);
            }
            __syncthreads();

            const float s0 = red[oc * 8 + orow]       + red[512 + oc * 8 + orow];
            const float s1 = red[(oc + 1) * 8 + orow] + red[512 + (oc + 1) * 8 + orow];
            v0 = tanhf(s0 + xav.x + bg.x);
            v1 = tanhf(s1 + xav.y + bg.y);
        }

        {
            float2* hdst = (float2*)&g_h[(s + 1) & 1][(size_t)grow * HH + gcol];
            asm volatile("st.global.cg.v2.f32 [%0], {%1, %2};"
                         :: "l"(hdst), "f"(v0), "f"(v1));
        }
        __syncthreads();

        if (s < SS - 1 && tid == 0) {
            asm volatile("st.release.gpu.u32 [%0], %1;"
                         :: "l"(my_flag), "r"((unsigned)(s + 1)));
        }

        {
            float2 yv; yv.x = v0; yv.y = v1;
            *(float2*)&out[(((size_t)b_idx * SS + s) * LL + l_idx) * HH + gcol] = yv;
            if (s == SS - 1) {
                *(float2*)&out[Y_ELEMS + (size_t)grow * HH + gcol] = yv;
            } else {
                xav = *(const float2*)&g_xa[((size_t)b_idx * SS + (s + 1)) * HH + gcol];
            }
        }
    }
}

// =============================================================================
// launch
// =============================================================================
extern "C" void kernel_launch(void* const* d_in, const int* in_sizes, int n_in,
                              void* d_out, int out_size)
{
    const float* x    = (const float*)d_in[0];
    const float* W_ih = (const float*)d_in[1];
    const float* b_ih = (const float*)d_in[2];
    const float* W_hh = (const float*)d_in[3];
    const float* b_hh = (const float*)d_in[4];
    float* out = (float*)d_out;

    // Reset step flags (graph-replay safety)
    reset_flags_kernel<<<1, 128>>>();

    // Kernel A v2: staged tf32 mma GEMM
    dim3 gridA(HH / 128, MX / 128);   // (4, 256)
    gemm_xa_mma_kernel<<<gridA, 256>>>(x, W_ih, b_ih);

    // Kernel B: persistent recurrence
    rnn_persistent_kernel<<<GB_CTAS, 256>>>(W_hh, b_hh, out);
}